// round 1
// baseline (speedup 1.0000x reference)
#include <cuda_runtime.h>

// Leapfrog (kick-drift-kick) integrator in a softened point-mass potential.
//   accel(q) = -GM * q / (r * (r + A_SCALE)^2 + 1e-12),  r = |q|
// GM = 1, A_SCALE = 1.
//
// Inputs (metadata order):
//   d_in[0] : ts        float32 [N]
//   d_in[1] : w0_lead   float32 [N,6]  (q,p)
//   d_in[2] : w0_trail  float32 [N,6]
//   d_in[3] : n_steps   int32 scalar
// Output: float32 [2N, 6], row 2*i = trail[i], row 2*i+1 = lead[i].

__device__ __forceinline__ void accel(float qx, float qy, float qz,
                                      float& ax, float& ay, float& az) {
    float r2 = fmaf(qx, qx, fmaf(qy, qy, qz * qz));
    float r  = sqrtf(r2);
    float rp = r + 1.0f;                       // r + A_SCALE
    float denom = fmaf(r * rp, rp, 1e-12f);    // r*(r+1)^2 + 1e-12
    float inv = -1.0f / denom;                 // fold GM and sign
    ax = qx * inv;
    ay = qy * inv;
    az = qz * inv;
}

__global__ void __launch_bounds__(256)
leapfrog_kernel(const float* __restrict__ ts,
                const float* __restrict__ w0_lead,
                const float* __restrict__ w0_trail,
                const int*   __restrict__ n_steps_ptr,
                float* __restrict__ out,
                int N) {
    int tid = blockIdx.x * blockDim.x + threadIdx.x;
    if (tid >= 2 * N) return;

    int b = (tid >= N) ? 1 : 0;        // 0 = trail, 1 = lead
    int i = tid - b * N;

    const float* __restrict__ w0 = b ? w0_lead : w0_trail;

    int n_steps = *n_steps_ptr;
    float t_f = ts[N - 1] + 0.001f;    // broadcast, L2-resident
    float dt = (t_f - ts[i]) / (float)n_steps;
    float hdt = 0.5f * dt;

    // Row i is 24 bytes -> 8-byte aligned: three float2 loads.
    const float2* __restrict__ row = reinterpret_cast<const float2*>(w0 + 6 * i);
    float2 v0 = row[0];
    float2 v1 = row[1];
    float2 v2 = row[2];
    float qx = v0.x, qy = v0.y, qz = v1.x;
    float px = v1.y, py = v2.x, pz = v2.y;

    float ax, ay, az;
    #pragma unroll 4
    for (int s = 0; s < n_steps; ++s) {
        // half kick
        accel(qx, qy, qz, ax, ay, az);
        px = fmaf(hdt, ax, px);
        py = fmaf(hdt, ay, py);
        pz = fmaf(hdt, az, pz);
        // drift
        qx = fmaf(dt, px, qx);
        qy = fmaf(dt, py, qy);
        qz = fmaf(dt, pz, qz);
        // half kick
        accel(qx, qy, qz, ax, ay, az);
        px = fmaf(hdt, ax, px);
        py = fmaf(hdt, ay, py);
        pz = fmaf(hdt, az, pz);
    }

    int orow = 2 * i + b;
    float2* __restrict__ orow_p = reinterpret_cast<float2*>(out + 6 * orow);
    orow_p[0] = make_float2(qx, qy);
    orow_p[1] = make_float2(qz, px);
    orow_p[2] = make_float2(py, pz);
}

extern "C" void kernel_launch(void* const* d_in, const int* in_sizes, int n_in,
                              void* d_out, int out_size) {
    const float* ts       = (const float*)d_in[0];
    const float* w0_lead  = (const float*)d_in[1];
    const float* w0_trail = (const float*)d_in[2];
    const int*   n_steps  = (const int*)d_in[3];
    float* out = (float*)d_out;

    int N = in_sizes[0];
    int total = 2 * N;
    int threads = 256;
    int blocks = (total + threads - 1) / threads;
    leapfrog_kernel<<<blocks, threads>>>(ts, w0_lead, w0_trail, n_steps, out, N);
}

// round 2
// speedup vs baseline: 1.5000x; 1.5000x over previous
#include <cuda_runtime.h>

// Leapfrog (KDK) integrator, softened point mass: a = -q / (r*(r+1)^2 + 1e-12).
//
// Optimizations vs v1:
//  - Fused kicks: closing half-kick of step s + opening half-kick of step s+1
//    evaluate accel at the same q -> fuse to one full kick. 65 accel evals
//    instead of 128 per particle.
//  - sqrt.approx / rcp.approx (1 MUFU each, no Newton refinement tail).
//  - f32x2 packed math: each thread integrates the (trail, lead) pair for
//    index i (identical dt), with all FMA-pipe work in packed fma.rn.f32x2.
//  - Output rows 2i (trail) and 2i+1 (lead) are contiguous: 3x STG.128.
//
// Inputs: d_in[0]=ts f32[N], d_in[1]=w0_lead f32[N,6], d_in[2]=w0_trail f32[N,6],
//         d_in[3]=n_steps i32. Output f32[2N,6].

typedef unsigned long long u64;

__device__ __forceinline__ u64 pk2(float lo, float hi) {
    u64 r; asm("mov.b64 %0, {%1, %2};" : "=l"(r) : "f"(lo), "f"(hi)); return r;
}
__device__ __forceinline__ void upk2(u64 v, float& lo, float& hi) {
    asm("mov.b64 {%0, %1}, %2;" : "=f"(lo), "=f"(hi) : "l"(v));
}
__device__ __forceinline__ u64 fma2(u64 a, u64 b, u64 c) {
    u64 d; asm("fma.rn.f32x2 %0, %1, %2, %3;" : "=l"(d) : "l"(a), "l"(b), "l"(c)); return d;
}
__device__ __forceinline__ u64 mul2(u64 a, u64 b) {
    u64 d; asm("mul.rn.f32x2 %0, %1, %2;" : "=l"(d) : "l"(a), "l"(b)); return d;
}
__device__ __forceinline__ u64 add2(u64 a, u64 b) {
    u64 d; asm("add.rn.f32x2 %0, %1, %2;" : "=l"(d) : "l"(a), "l"(b)); return d;
}
__device__ __forceinline__ float sqrt_ap(float x) {
    float r; asm("sqrt.approx.f32 %0, %1;" : "=f"(r) : "f"(x)); return r;
}
__device__ __forceinline__ float rcp_ap(float x) {
    float r; asm("rcp.approx.f32 %0, %1;" : "=f"(r) : "f"(x)); return r;
}

struct State {
    u64 qx, qy, qz, px, py, pz;
};

// p += coef * accel(q), with ncoef2 = packed(-coef, -coef) pre-negated so the
// sign of accel folds into one packed mul.
__device__ __forceinline__ void kick(State& s, u64 ncoef2, u64 one2, u64 eps2) {
    u64 r2 = fma2(s.qx, s.qx, fma2(s.qy, s.qy, mul2(s.qz, s.qz)));
    float r2lo, r2hi;  upk2(r2, r2lo, r2hi);
    u64 r  = pk2(sqrt_ap(r2lo), sqrt_ap(r2hi));
    u64 rp = add2(r, one2);                     // r + 1
    u64 den = fma2(mul2(r, rp), rp, eps2);      // r*(r+1)^2 + 1e-12
    float dlo, dhi;    upk2(den, dlo, dhi);
    u64 inv = pk2(rcp_ap(dlo), rcp_ap(dhi));
    u64 sc  = mul2(inv, ncoef2);                // -coef / den
    s.px = fma2(sc, s.qx, s.px);
    s.py = fma2(sc, s.qy, s.py);
    s.pz = fma2(sc, s.qz, s.pz);
}

__device__ __forceinline__ void drift(State& s, u64 dt2) {
    s.qx = fma2(dt2, s.px, s.qx);
    s.qy = fma2(dt2, s.py, s.qy);
    s.qz = fma2(dt2, s.pz, s.qz);
}

__global__ void __launch_bounds__(64)
leapfrog_pair_kernel(const float* __restrict__ ts,
                     const float* __restrict__ w0_lead,
                     const float* __restrict__ w0_trail,
                     const int*   __restrict__ n_steps_ptr,
                     float* __restrict__ out,
                     int N) {
    int i = blockIdx.x * blockDim.x + threadIdx.x;
    if (i >= N) return;

    int n_steps = *n_steps_ptr;
    float t_f = ts[N - 1] + 0.001f;
    float dt  = (t_f - ts[i]) / (float)n_steps;
    float hdt = 0.5f * dt;

    u64 dt2  = pk2(dt, dt);
    u64 ndt2 = pk2(-dt, -dt);
    u64 nh2  = pk2(-hdt, -hdt);
    u64 one2 = pk2(1.0f, 1.0f);
    u64 eps2 = pk2(1e-12f, 1e-12f);

    // Load both rows; pack lo=trail, hi=lead.
    const float2* __restrict__ rl = reinterpret_cast<const float2*>(w0_lead  + 6 * i);
    const float2* __restrict__ rt = reinterpret_cast<const float2*>(w0_trail + 6 * i);
    float2 l0 = rl[0], l1 = rl[1], l2 = rl[2];
    float2 t0 = rt[0], t1 = rt[1], t2 = rt[2];

    State s;
    s.qx = pk2(t0.x, l0.x);
    s.qy = pk2(t0.y, l0.y);
    s.qz = pk2(t1.x, l1.x);
    s.px = pk2(t1.y, l1.y);
    s.py = pk2(t2.x, l2.x);
    s.pz = pk2(t2.y, l2.y);

    // KDK with fused interior kicks:
    //   half kick; (n-1) x (drift; full kick); drift; half kick.
    kick(s, nh2, one2, eps2);
    #pragma unroll 4
    for (int it = 0; it < n_steps - 1; ++it) {
        drift(s, dt2);
        kick(s, ndt2, one2, eps2);
    }
    drift(s, dt2);
    kick(s, nh2, one2, eps2);

    // Unpack and store: row 2i = trail, row 2i+1 = lead -> 48 contiguous bytes.
    float qxt, qxl, qyt, qyl, qzt, qzl, pxt, pxl, pyt, pyl, pzt, pzl;
    upk2(s.qx, qxt, qxl); upk2(s.qy, qyt, qyl); upk2(s.qz, qzt, qzl);
    upk2(s.px, pxt, pxl); upk2(s.py, pyt, pyl); upk2(s.pz, pzt, pzl);

    float4* __restrict__ o = reinterpret_cast<float4*>(out + 12 * i);
    o[0] = make_float4(qxt, qyt, qzt, pxt);
    o[1] = make_float4(pyt, pzt, qxl, qyl);
    o[2] = make_float4(qzl, pxl, pyl, pzl);
}

extern "C" void kernel_launch(void* const* d_in, const int* in_sizes, int n_in,
                              void* d_out, int out_size) {
    const float* ts       = (const float*)d_in[0];
    const float* w0_lead  = (const float*)d_in[1];
    const float* w0_trail = (const float*)d_in[2];
    const int*   n_steps  = (const int*)d_in[3];
    float* out = (float*)d_out;

    int N = in_sizes[0];
    int threads = 64;
    int blocks = (N + threads - 1) / threads;
    leapfrog_pair_kernel<<<blocks, threads>>>(ts, w0_lead, w0_trail, n_steps, out, N);
}